// round 3
// baseline (speedup 1.0000x reference)
#include <cuda_runtime.h>

#define TPB 128
typedef unsigned long long ull;

// x:      (4, 32, 56, 56) f32
// weight: (4, 4, 9, 8, 16) f32   [o][p][k][l][d]
// out:    (4, 64, 56, 56) f32    channel = o*16 + d
//
// Two lanes per site (even lane: d0-7, odd lane: d8-15), f32x2 packed math.
// priors + routing register-resident; weights staged in shared.
// Iter-0 routing uses exact-uniform softmax (logits start at zero).

__device__ __forceinline__ ull fma2(ull a, ull b, ull c) {
    ull d;
    asm("fma.rn.f32x2 %0, %1, %2, %3;" : "=l"(d) : "l"(a), "l"(b), "l"(c));
    return d;
}
__device__ __forceinline__ ull pack2(float x, float y) {
    ull r;
    asm("mov.b64 %0, {%1, %2};" : "=l"(r) : "f"(x), "f"(y));
    return r;
}
__device__ __forceinline__ float2 unpack2(ull v) {
    float2 r;
    asm("mov.b64 {%0, %1}, %2;" : "=f"(r.x), "=f"(r.y) : "l"(v));
    return r;
}

__global__ void __launch_bounds__(TPB, 4) caps_kernel(
    const float* __restrict__ x,
    const float* __restrict__ wgt,
    float* __restrict__ out)
{
    __shared__ float sw[4608];  // weight[o]: [p][k][l][d] = 4*9*8*16
    const int o = blockIdx.y;
    const int n = blockIdx.z;

    {
        const float4* src = reinterpret_cast<const float4*>(wgt) + o * 1152;
        float4* dst = reinterpret_cast<float4*>(sw);
        #pragma unroll
        for (int i = 0; i < 9; ++i)
            dst[threadIdx.x + i * TPB] = src[threadIdx.x + i * TPB];
    }
    __syncthreads();

    const int tid  = threadIdx.x;
    const int half = tid & 1;                               // 8-d half owned
    const int s    = blockIdx.x * (TPB / 2) + (tid >> 1);   // site (3136 = 49*64)
    const int h = s / 56;
    const int w = s - h * 56;

    const bool ht = (h > 0), hb = (h < 55);
    const bool wl = (w > 0), wr = (w < 55);

    ull outs[4];
    #pragma unroll
    for (int j = 0; j < 4; ++j) outs[j] = 0ull;

    #pragma unroll 1
    for (int p = 0; p < 4; ++p) {
        // ---- priors[k][own 8 d's] as 4 f32x2 pairs per k ----
        ull pri[36];
        #pragma unroll
        for (int i = 0; i < 36; ++i) pri[i] = 0ull;

        const float* xc0 = x + (n * 32 + p * 8) * 3136 + s;
        const ulonglong2* swu2 = reinterpret_cast<const ulonglong2*>(sw);

        #pragma unroll 2
        for (int l = 0; l < 8; ++l) {
            const float* xc = xc0 + l * 3136;
            float pt[9];
            pt[0] = (ht && wl) ? __ldg(xc - 57) : 0.0f;
            pt[1] = (ht)       ? __ldg(xc - 56) : 0.0f;
            pt[2] = (ht && wr) ? __ldg(xc - 55) : 0.0f;
            pt[3] = (wl)       ? __ldg(xc - 1)  : 0.0f;
            pt[4] =              __ldg(xc);
            pt[5] = (wr)       ? __ldg(xc + 1)  : 0.0f;
            pt[6] = (hb && wl) ? __ldg(xc + 55) : 0.0f;
            pt[7] = (hb)       ? __ldg(xc + 56) : 0.0f;
            pt[8] = (hb && wr) ? __ldg(xc + 57) : 0.0f;

            const ulonglong2* wb = swu2 + (p * 72 + l) * 4 + half * 2;
            #pragma unroll
            for (int k = 0; k < 9; ++k) {
                const ulonglong2 wa = wb[k * 32];       // d+0..3
                const ulonglong2 wc = wb[k * 32 + 1];   // d+4..7
                const ull pkk = pack2(pt[k], pt[k]);
                pri[k*4 + 0] = fma2(pkk, wa.x, pri[k*4 + 0]);
                pri[k*4 + 1] = fma2(pkk, wa.y, pri[k*4 + 1]);
                pri[k*4 + 2] = fma2(pkk, wc.x, pri[k*4 + 2]);
                pri[k*4 + 3] = fma2(pkk, wc.y, pri[k*4 + 3]);
            }
        }

        // ---- dynamic routing ----
        float logits[9];

        // ===== iteration 0: logits are all zero -> probs exactly uniform =====
        {
            const float ninth = __fdividef(1.0f, 9.0f);
            const ull np = pack2(ninth, ninth);
            ull sv[4];
            #pragma unroll
            for (int j = 0; j < 4; ++j) sv[j] = 0ull;
            #pragma unroll
            for (int k = 0; k < 9; ++k) {
                #pragma unroll
                for (int j = 0; j < 4; ++j)
                    sv[j] = fma2(np, pri[k*4 + j], sv[j]);
            }

            ull acc = 0ull;
            #pragma unroll
            for (int j = 0; j < 4; ++j) acc = fma2(sv[j], sv[j], acc);
            const float2 a2 = unpack2(acc);
            const float sqo = a2.x + a2.y;
            const float sq = sqo + __shfl_xor_sync(0xffffffffu, sqo, 1);
            const float f = sqrtf(sq) * __fdividef(1.0f, 1.0f + sq);

            #pragma unroll
            for (int k = 0; k < 9; ++k) {
                ull da = 0ull;
                #pragma unroll
                for (int j = 0; j < 4; ++j)
                    da = fma2(pri[k*4 + j], sv[j], da);
                const float2 d2 = unpack2(da);
                const float dlo = d2.x + d2.y;
                const float dl = dlo + __shfl_xor_sync(0xffffffffu, dlo, 1);
                logits[k] = f * dl;
            }
        }

        // ===== iterations 1 and 2 =====
        #pragma unroll 1
        for (int it = 1; it < 3; ++it) {
            float mx = logits[0];
            #pragma unroll
            for (int k = 1; k < 9; ++k) mx = fmaxf(mx, logits[k]);
            float pr[9];
            float sum = 0.0f;
            #pragma unroll
            for (int k = 0; k < 9; ++k) {
                pr[k] = __expf(logits[k] - mx);
                sum += pr[k];
            }
            const float inv = __fdividef(1.0f, sum);

            ull sv[4];
            #pragma unroll
            for (int j = 0; j < 4; ++j) sv[j] = 0ull;
            #pragma unroll
            for (int k = 0; k < 9; ++k) {
                const float pk = pr[k] * inv;
                const ull pkk = pack2(pk, pk);
                #pragma unroll
                for (int j = 0; j < 4; ++j)
                    sv[j] = fma2(pkk, pri[k*4 + j], sv[j]);
            }

            ull acc = 0ull;
            #pragma unroll
            for (int j = 0; j < 4; ++j) acc = fma2(sv[j], sv[j], acc);
            const float2 a2 = unpack2(acc);
            const float sqo = a2.x + a2.y;
            const float sq = sqo + __shfl_xor_sync(0xffffffffu, sqo, 1);
            const float f = sqrtf(sq) * __fdividef(1.0f, 1.0f + sq);

            if (it == 1) {
                #pragma unroll
                for (int k = 0; k < 9; ++k) {
                    ull da = 0ull;
                    #pragma unroll
                    for (int j = 0; j < 4; ++j)
                        da = fma2(pri[k*4 + j], sv[j], da);
                    const float2 d2 = unpack2(da);
                    const float dlo = d2.x + d2.y;
                    const float dl = dlo + __shfl_xor_sync(0xffffffffu, dlo, 1);
                    logits[k] = fmaf(f, dl, logits[k]);
                }
            } else {
                const ull ff = pack2(f, f);
                #pragma unroll
                for (int j = 0; j < 4; ++j)
                    outs[j] = fma2(sv[j], ff, outs[j]);
            }
        }
    }

    // ---- write: out[n][o*16 + half*8 + j][h][w] ----
    float* ob = out + ((n * 4 + o) * 16 + half * 8) * 3136 + s;
    #pragma unroll
    for (int j = 0; j < 4; ++j) {
        const float2 v = unpack2(outs[j]);
        ob[(2*j    ) * 3136] = v.x;
        ob[(2*j + 1) * 3136] = v.y;
    }
}

extern "C" void kernel_launch(void* const* d_in, const int* in_sizes, int n_in,
                              void* d_out, int out_size) {
    const float* x   = (const float*)d_in[0];
    const float* wgt = (const float*)d_in[1];
    float* out = (float*)d_out;

    dim3 grid(3136 / (TPB / 2), 4, 4);  // (49, o=4, n=4)
    caps_kernel<<<grid, TPB>>>(x, wgt, out);
}

// round 4
// speedup vs baseline: 1.0721x; 1.0721x over previous
#include <cuda_runtime.h>

#define TPB 128
typedef unsigned long long ull;

// x:      (4, 32, 56, 56) f32
// weight: (4, 4, 9, 8, 16) f32   [o][p][k][l][d]
// out:    (4, 64, 56, 56) f32    channel = o*16 + d
//
// Two lanes per site (even lane: d0-7, odd lane: d8-15), f32x2 packed math.
// priors + routing register-resident; weights staged in shared.
// Iter-0 routing uses exact-uniform softmax (logits start at zero).
// l=0 / k=0 accumulator folds avoid zero-init MOVs.

__device__ __forceinline__ ull fma2(ull a, ull b, ull c) {
    ull d;
    asm("fma.rn.f32x2 %0, %1, %2, %3;" : "=l"(d) : "l"(a), "l"(b), "l"(c));
    return d;
}
__device__ __forceinline__ ull mul2(ull a, ull b) {
    ull d;
    asm("mul.rn.f32x2 %0, %1, %2;" : "=l"(d) : "l"(a), "l"(b));
    return d;
}
__device__ __forceinline__ ull pack2(float x, float y) {
    ull r;
    asm("mov.b64 %0, {%1, %2};" : "=l"(r) : "f"(x), "f"(y));
    return r;
}
__device__ __forceinline__ float2 unpack2(ull v) {
    float2 r;
    asm("mov.b64 {%0, %1}, %2;" : "=f"(r.x), "=f"(r.y) : "l"(v));
    return r;
}

__global__ void __launch_bounds__(TPB, 3) caps_kernel(
    const float* __restrict__ x,
    const float* __restrict__ wgt,
    float* __restrict__ out)
{
    __shared__ float sw[4608];  // weight[o]: [p][k][l][d] = 4*9*8*16
    const int o = blockIdx.y;
    const int n = blockIdx.z;

    {
        const float4* src = reinterpret_cast<const float4*>(wgt) + o * 1152;
        float4* dst = reinterpret_cast<float4*>(sw);
        #pragma unroll
        for (int i = 0; i < 9; ++i)
            dst[threadIdx.x + i * TPB] = src[threadIdx.x + i * TPB];
    }
    __syncthreads();

    const int tid  = threadIdx.x;
    const int half = tid & 1;                               // 8-d half owned
    const int s    = blockIdx.x * (TPB / 2) + (tid >> 1);   // site (3136 = 49*64)
    const int h = s / 56;
    const int w = s - h * 56;

    const bool ht = (h > 0), hb = (h < 55);
    const bool wl = (w > 0), wr = (w < 55);

    ull outs[4];
    #pragma unroll
    for (int j = 0; j < 4; ++j) outs[j] = 0ull;

    #pragma unroll 1
    for (int p = 0; p < 4; ++p) {
        // ---- priors[k][own 8 d's] as 4 f32x2 pairs per k ----
        ull pri[36];

        const float* xc0 = x + (n * 32 + p * 8) * 3136 + s;
        const ulonglong2* swu2 = reinterpret_cast<const ulonglong2*>(sw);

        #pragma unroll 2
        for (int l = 0; l < 8; ++l) {
            const float* xc = xc0 + l * 3136;
            float pt[9];
            pt[0] = (ht && wl) ? __ldg(xc - 57) : 0.0f;
            pt[1] = (ht)       ? __ldg(xc - 56) : 0.0f;
            pt[2] = (ht && wr) ? __ldg(xc - 55) : 0.0f;
            pt[3] = (wl)       ? __ldg(xc - 1)  : 0.0f;
            pt[4] =              __ldg(xc);
            pt[5] = (wr)       ? __ldg(xc + 1)  : 0.0f;
            pt[6] = (hb && wl) ? __ldg(xc + 55) : 0.0f;
            pt[7] = (hb)       ? __ldg(xc + 56) : 0.0f;
            pt[8] = (hb && wr) ? __ldg(xc + 57) : 0.0f;

            const ulonglong2* wb = swu2 + (p * 72 + l) * 4 + half * 2;
            if (l == 0) {
                #pragma unroll
                for (int k = 0; k < 9; ++k) {
                    const ulonglong2 wa = wb[k * 32];
                    const ulonglong2 wc = wb[k * 32 + 1];
                    const ull pkk = pack2(pt[k], pt[k]);
                    pri[k*4 + 0] = mul2(pkk, wa.x);
                    pri[k*4 + 1] = mul2(pkk, wa.y);
                    pri[k*4 + 2] = mul2(pkk, wc.x);
                    pri[k*4 + 3] = mul2(pkk, wc.y);
                }
            } else {
                #pragma unroll
                for (int k = 0; k < 9; ++k) {
                    const ulonglong2 wa = wb[k * 32];
                    const ulonglong2 wc = wb[k * 32 + 1];
                    const ull pkk = pack2(pt[k], pt[k]);
                    pri[k*4 + 0] = fma2(pkk, wa.x, pri[k*4 + 0]);
                    pri[k*4 + 1] = fma2(pkk, wa.y, pri[k*4 + 1]);
                    pri[k*4 + 2] = fma2(pkk, wc.x, pri[k*4 + 2]);
                    pri[k*4 + 3] = fma2(pkk, wc.y, pri[k*4 + 3]);
                }
            }
        }

        // ---- dynamic routing ----
        float logits[9];

        // ===== iteration 0: logits all zero -> probs exactly uniform =====
        {
            const float ninth = __fdividef(1.0f, 9.0f);
            const ull np = pack2(ninth, ninth);
            ull sv[4];
            #pragma unroll
            for (int j = 0; j < 4; ++j) sv[j] = mul2(np, pri[j]);
            #pragma unroll
            for (int k = 1; k < 9; ++k) {
                #pragma unroll
                for (int j = 0; j < 4; ++j)
                    sv[j] = fma2(np, pri[k*4 + j], sv[j]);
            }

            ull acc = mul2(sv[0], sv[0]);
            #pragma unroll
            for (int j = 1; j < 4; ++j) acc = fma2(sv[j], sv[j], acc);
            const float2 a2 = unpack2(acc);
            const float sqo = a2.x + a2.y;
            const float sq = sqo + __shfl_xor_sync(0xffffffffu, sqo, 1);
            const float f = sqrtf(sq) * __fdividef(1.0f, 1.0f + sq);

            #pragma unroll
            for (int k = 0; k < 9; ++k) {
                ull da = mul2(pri[k*4], sv[0]);
                #pragma unroll
                for (int j = 1; j < 4; ++j)
                    da = fma2(pri[k*4 + j], sv[j], da);
                const float2 d2 = unpack2(da);
                const float dlo = d2.x + d2.y;
                const float dl = dlo + __shfl_xor_sync(0xffffffffu, dlo, 1);
                logits[k] = f * dl;
            }
        }

        // ===== iterations 1 and 2 =====
        #pragma unroll 1
        for (int it = 1; it < 3; ++it) {
            float mx = logits[0];
            #pragma unroll
            for (int k = 1; k < 9; ++k) mx = fmaxf(mx, logits[k]);
            float pr[9];
            float sum = 0.0f;
            #pragma unroll
            for (int k = 0; k < 9; ++k) {
                pr[k] = __expf(logits[k] - mx);
                sum += pr[k];
            }
            const float inv = __fdividef(1.0f, sum);

            ull sv[4];
            {
                const float pk0 = pr[0] * inv;
                const ull pkk0 = pack2(pk0, pk0);
                #pragma unroll
                for (int j = 0; j < 4; ++j) sv[j] = mul2(pkk0, pri[j]);
            }
            #pragma unroll
            for (int k = 1; k < 9; ++k) {
                const float pk = pr[k] * inv;
                const ull pkk = pack2(pk, pk);
                #pragma unroll
                for (int j = 0; j < 4; ++j)
                    sv[j] = fma2(pkk, pri[k*4 + j], sv[j]);
            }

            ull acc = mul2(sv[0], sv[0]);
            #pragma unroll
            for (int j = 1; j < 4; ++j) acc = fma2(sv[j], sv[j], acc);
            const float2 a2 = unpack2(acc);
            const float sqo = a2.x + a2.y;
            const float sq = sqo + __shfl_xor_sync(0xffffffffu, sqo, 1);
            const float f = sqrtf(sq) * __fdividef(1.0f, 1.0f + sq);

            if (it == 1) {
                #pragma unroll
                for (int k = 0; k < 9; ++k) {
                    ull da = mul2(pri[k*4], sv[0]);
                    #pragma unroll
                    for (int j = 1; j < 4; ++j)
                        da = fma2(pri[k*4 + j], sv[j], da);
                    const float2 d2 = unpack2(da);
                    const float dlo = d2.x + d2.y;
                    const float dl = dlo + __shfl_xor_sync(0xffffffffu, dlo, 1);
                    logits[k] = fmaf(f, dl, logits[k]);
                }
            } else {
                const ull ff = pack2(f, f);
                #pragma unroll
                for (int j = 0; j < 4; ++j)
                    outs[j] = fma2(sv[j], ff, outs[j]);
            }
        }
    }

    // ---- write: out[n][o*16 + half*8 + j][h][w] ----
    float* ob = out + ((n * 4 + o) * 16 + half * 8) * 3136 + s;
    #pragma unroll
    for (int j = 0; j < 4; ++j) {
        const float2 v = unpack2(outs[j]);
        ob[(2*j    ) * 3136] = v.x;
        ob[(2*j + 1) * 3136] = v.y;
    }
}

extern "C" void kernel_launch(void* const* d_in, const int* in_sizes, int n_in,
                              void* d_out, int out_size) {
    const float* x   = (const float*)d_in[0];
    const float* wgt = (const float*)d_in[1];
    float* out = (float*)d_out;

    dim3 grid(3136 / (TPB / 2), 4, 4);  // (49, o=4, n=4)
    caps_kernel<<<grid, TPB>>>(x, wgt, out);
}